// round 2
// baseline (speedup 1.0000x reference)
#include <cuda_runtime.h>
#include <cuda_bf16.h>

// TD(lambda) backward scan with per-timestep lambda.
//   gamma   = max(tanh(raw_gamma), EPS)
//   lam_t   = max(tanh(raw_lambd[t]), EPS)
//   ret_{S} = values[b, S]
//   for t = S-1 .. 0:
//     boot  = (1-lam_t)*values[b,t+1] + lam_t*ret_{t+1}
//     ret_t = rewards[b,t] + gamma*(1-dones[b,t])*boot
//   out[b,t] = ret_t
//
// One thread per batch row; unroll-8 backward groups with one-group-ahead
// prefetch so ~200 B/thread of loads stay in flight (HBM-bound kernel).

#define B_TOT 32768
#define S_LEN 512
#define EPS_F 1e-8f

static constexpr int U  = 8;           // timesteps per group
static constexpr int NG = S_LEN / U;   // 64 groups

__device__ __forceinline__ void load_group(
    const float* __restrict__ vrow,
    const float* __restrict__ rrow,
    const float* __restrict__ drow,
    int g, float* rv, float* dv, float* vv)
{
    const int base = g * U;
    float4 a = *(const float4*)(rrow + base);
    float4 b = *(const float4*)(rrow + base + 4);
    rv[0] = a.x; rv[1] = a.y; rv[2] = a.z; rv[3] = a.w;
    rv[4] = b.x; rv[5] = b.y; rv[6] = b.z; rv[7] = b.w;
    float4 c = *(const float4*)(drow + base);
    float4 e = *(const float4*)(drow + base + 4);
    dv[0] = c.x; dv[1] = c.y; dv[2] = c.z; dv[3] = c.w;
    dv[4] = e.x; dv[5] = e.y; dv[6] = e.z; dv[7] = e.w;
    // values row has length S+1 = 513 (odd) -> scalar loads (every byte of
    // each 128B line is still consumed by this thread over the row).
#pragma unroll
    for (int j = 0; j < U; j++)
        vv[j] = __ldg(vrow + base + j + 1);
}

__global__ __launch_bounds__(128)
void gamma_lambda_kernel(
    const float* __restrict__ values,    // [B, S+1]
    const float* __restrict__ rewards,   // [B, S]
    const float* __restrict__ dones,     // [B, S]
    const float* __restrict__ raw_gamma, // [1]
    const float* __restrict__ raw_lambd, // [S]
    float* __restrict__ out)             // [B, S]
{
    __shared__ float s_lam[S_LEN];
    __shared__ float s_gamma;

    for (int i = threadIdx.x; i < S_LEN; i += blockDim.x)
        s_lam[i] = fmaxf(tanhf(raw_lambd[i]), EPS_F);
    if (threadIdx.x == 0)
        s_gamma = fmaxf(tanhf(raw_gamma[0]), EPS_F);
    __syncthreads();

    const int b = blockIdx.x * blockDim.x + threadIdx.x;
    if (b >= B_TOT) return;

    const float* vrow = values  + (size_t)b * (S_LEN + 1);
    const float* rrow = rewards + (size_t)b * S_LEN;
    const float* drow = dones   + (size_t)b * S_LEN;
    float*       orow = out     + (size_t)b * S_LEN;

    const float gamma = s_gamma;
    float ret = __ldg(vrow + S_LEN);   // bootstrap: values[b, S]

    float rv[U], dv[U], vv[U];
    load_group(vrow, rrow, drow, NG - 1, rv, dv, vv);

    for (int g = NG - 1; g >= 0; --g) {
        // Prefetch next (lower) group BEFORE walking the dependent chain.
        float nr[U], nd[U], nv[U];
        if (g > 0)
            load_group(vrow, rrow, drow, g - 1, nr, nd, nv);

        float o[U];
#pragma unroll
        for (int j = U - 1; j >= 0; --j) {
            const float lam  = s_lam[g * U + j];      // warp-uniform smem broadcast
            const float vn   = vv[j];
            const float boot = fmaf(lam, ret - vn, vn);        // (1-lam)v + lam*ret
            const float coef = gamma * (1.0f - dv[j]);          // off the chain
            ret = fmaf(coef, boot, rv[j]);
            o[j] = ret;
        }

        *(float4*)(orow + g * U)     = make_float4(o[0], o[1], o[2], o[3]);
        *(float4*)(orow + g * U + 4) = make_float4(o[4], o[5], o[6], o[7]);

        if (g > 0) {
#pragma unroll
            for (int j = 0; j < U; j++) { rv[j] = nr[j]; dv[j] = nd[j]; vv[j] = nv[j]; }
        }
    }
}

extern "C" void kernel_launch(void* const* d_in, const int* in_sizes, int n_in,
                              void* d_out, int out_size)
{
    const float* values    = (const float*)d_in[0];
    const float* rewards   = (const float*)d_in[1];
    const float* dones     = (const float*)d_in[2];
    const float* raw_gamma = (const float*)d_in[3];
    const float* raw_lambd = (const float*)d_in[4];
    float* out = (float*)d_out;

    const int threads = 128;
    const int blocks  = (B_TOT + threads - 1) / threads;   // 256
    gamma_lambda_kernel<<<blocks, threads>>>(values, rewards, dones,
                                             raw_gamma, raw_lambd, out);
}

// round 3
// speedup vs baseline: 1.4666x; 1.4666x over previous
#include <cuda_runtime.h>
#include <cuda_bf16.h>

// TD(lambda) backward scan, warp-per-row parallel formulation.
//
// Recurrence: ret_t = a_t * ret_{t+1} + b_t
//   a_t = gamma*(1-d_t)*lam_t
//   b_t = r_t + gamma*(1-d_t)*(1-lam_t)*v_{t+1}
// Affine maps compose associatively -> per-lane serial compose over a
// 16-element contiguous segment, warp suffix scan (shfl) over 32 segments,
// then per-lane replay. All global traffic is staged through padded smem so
// loads AND stores are fully coalesced (min L1tex wavefronts).

#define B_TOT 32768
#define S_LEN 512
#define EPS_F 1e-8f

static constexpr int WARPS_PER_BLOCK = 4;     // 128 threads
static constexpr int SEG = 16;                // elements per lane
static constexpr int PADDED = S_LEN + S_LEN / SEG;  // 544: +1 pad per 16

__device__ __forceinline__ int padidx(int i) { return i + (i >> 4); }

__global__ __launch_bounds__(WARPS_PER_BLOCK * 32)
void gamma_lambda_scan_kernel(
    const float* __restrict__ values,    // [B, S+1]
    const float* __restrict__ rewards,   // [B, S]
    const float* __restrict__ dones,     // [B, S]
    const float* __restrict__ raw_gamma, // [1]
    const float* __restrict__ raw_lambd, // [S]
    float* __restrict__ out)             // [B, S]
{
    __shared__ float s_lam[PADDED];
    __shared__ float s_r[WARPS_PER_BLOCK][PADDED];
    __shared__ float s_d[WARPS_PER_BLOCK][PADDED];
    __shared__ float s_v[WARPS_PER_BLOCK][PADDED];
    __shared__ float s_gamma;

    const int tid  = threadIdx.x;
    const int wid  = tid >> 5;
    const int lane = tid & 31;

    for (int i = tid; i < S_LEN; i += blockDim.x)
        s_lam[padidx(i)] = fmaxf(tanhf(raw_lambd[i]), EPS_F);
    if (tid == 0)
        s_gamma = fmaxf(tanhf(raw_gamma[0]), EPS_F);
    __syncthreads();

    const int row = blockIdx.x * WARPS_PER_BLOCK + wid;   // 32768 rows exactly
    const float gamma = s_gamma;

    const float* vrow = values  + (size_t)row * (S_LEN + 1);
    const float* rrow = rewards + (size_t)row * S_LEN;
    const float* drow = dones   + (size_t)row * S_LEN;
    float*       orow = out     + (size_t)row * S_LEN;

    // ---- Phase 1: coalesced stage of r, d, v_next into padded smem ----
    float* __restrict__ wr = s_r[wid];
    float* __restrict__ wd = s_d[wid];
    float* __restrict__ wv = s_v[wid];
#pragma unroll
    for (int k = 0; k < SEG; k++) {
        const int g = k * 32 + lane;
        const int p = padidx(g);
        wr[p] = rrow[g];
        wd[p] = drow[g];
        wv[p] = vrow[g + 1];       // v_next[t] = values[t+1]
    }
    __syncwarp();

    const float v_init = wv[padidx(S_LEN - 1)];   // values[row, S] (broadcast)

    // ---- Phase 2: per-lane backward compose over segment [lo, lo+15] ----
    // (A,B): ret_{lo} = A * ret_{lo+16} + B
    const int lo = lane * SEG;
    float A = 1.0f, Bc = 0.0f;
#pragma unroll
    for (int j = SEG - 1; j >= 0; --j) {
        const int p  = lane * (SEG + 1) + j;   // padidx(lo + j), conflict-free
        const float lam = s_lam[p];
        const float gd  = gamma - gamma * wd[p];     // gamma*(1-d)
        const float a   = gd * lam;
        const float b   = fmaf(gd - a, wv[p], wr[p]); // r + gd*(1-lam)*v
        Bc = fmaf(a, Bc, b);
        A  = a * A;
    }

    // ---- Phase 3: warp suffix-inclusive scan of affine maps ----
    // compose (A1,B1) after (A2,B2): x -> A1*(A2*x+B2)+B1
#pragma unroll
    for (int off = 1; off < 32; off <<= 1) {
        const float A2 = __shfl_down_sync(0xFFFFFFFFu, A,  off);
        const float B2 = __shfl_down_sync(0xFFFFFFFFu, Bc, off);
        if (lane + off < 32) {
            Bc = fmaf(A, B2, Bc);
            A  = A * A2;
        }
    }
    // exclusive: lane l needs suffix of lanes l+1..31 applied to v_init
    float Ae = __shfl_down_sync(0xFFFFFFFFu, A,  1);
    float Be = __shfl_down_sync(0xFFFFFFFFu, Bc, 1);
    if (lane == 31) { Ae = 1.0f; Be = 0.0f; }
    float ret = fmaf(Ae, v_init, Be);   // ret at right boundary of my segment

    // ---- Phase 4: replay segment, write outputs into smem (reuse s_r) ----
#pragma unroll
    for (int j = SEG - 1; j >= 0; --j) {
        const int p  = lane * (SEG + 1) + j;
        const float lam = s_lam[p];
        const float gd  = gamma - gamma * wd[p];
        const float a   = gd * lam;
        const float b   = fmaf(gd - a, wv[p], wr[p]);
        ret = fmaf(a, ret, b);
        wr[p] = ret;                 // own segment only: no race
    }
    __syncwarp();

    // ---- Phase 5: coalesced store ----
#pragma unroll
    for (int k = 0; k < SEG; k++) {
        const int g = k * 32 + lane;
        orow[g] = wr[padidx(g)];
    }
}

extern "C" void kernel_launch(void* const* d_in, const int* in_sizes, int n_in,
                              void* d_out, int out_size)
{
    const float* values    = (const float*)d_in[0];
    const float* rewards   = (const float*)d_in[1];
    const float* dones     = (const float*)d_in[2];
    const float* raw_gamma = (const float*)d_in[3];
    const float* raw_lambd = (const float*)d_in[4];
    float* out = (float*)d_out;

    const int threads = WARPS_PER_BLOCK * 32;            // 128
    const int blocks  = B_TOT / WARPS_PER_BLOCK;         // 8192
    gamma_lambda_scan_kernel<<<blocks, threads>>>(values, rewards, dones,
                                                  raw_gamma, raw_lambd, out);
}